// round 7
// baseline (speedup 1.0000x reference)
#include <cuda_runtime.h>
#include <cstdint>

#define NUM_BINS 32
#define MAXK     4
#define MAXU     100352
#define NMAXV    (2*MAXU)
#define NPAD     (NMAXV + 64)

typedef unsigned long long u64;

__device__ int   g_cnt[MAXU];
__device__ int4  g_list[MAXU];                   // packed (voxel<<5 | bin)
__device__ float g_xT[(size_t)64 * NPAD];        // transposed MLP output [c][v]
__device__ float g_xemp[64];                     // MLP(0) vector

// ---------------- packed f32x2 helpers -------------------------------------
__device__ __forceinline__ u64 pk2(float lo, float hi) {
    u64 r; asm("mov.b64 %0,{%1,%2};" : "=l"(r) : "f"(lo), "f"(hi)); return r;
}
__device__ __forceinline__ u64 dup2(float v) { return pk2(v, v); }
__device__ __forceinline__ void fma2(u64 &d, u64 a, u64 b) {
    asm("fma.rn.f32x2 %0,%1,%2,%0;" : "+l"(d) : "l"(a), "l"(b));
}
__device__ __forceinline__ float2 unpk(u64 v) {
    float2 r; asm("mov.b64 {%0,%1},%2;" : "=f"(r.x), "=f"(r.y) : "l"(v)); return r;
}
union F4U { float4 f; u64 u[2]; };

__device__ __forceinline__ float sigm(float x) {
    return __fdividef(1.f, 1.f + __expf(-x));
}

// ---------------------------------------------------------------- scatter ---
__global__ void scatter_kernel(const int* __restrict__ unq_inv,
                               const int* __restrict__ coords, int N) {
    int i = blockIdx.x * blockDim.x + threadIdx.x;
    if (i >= N) return;
    int p = unq_inv[i];
    int b = coords[4 * i + 1];
    int k = atomicAdd(&g_cnt[p], 1);
    if (k < MAXK) ((int*)g_list)[p * 4 + k] = (i << 5) | (b & 31);
}

// ------------------------------------------------------------------- mask ---
__global__ void mask_kernel(const int* __restrict__ cnt, float* __restrict__ out,
                            long long base, int n) {
    int i = blockIdx.x * blockDim.x + threadIdx.x;
    if (i < n) out[base + i] = (cnt[i] >= 2) ? 1.0f : 0.0f;
}

// ------------------------------------------------------------------- xemp ---
__global__ void xemp_kernel(const float* __restrict__ b1,
                            const float* __restrict__ W2,
                            const float* __restrict__ b2) {
    int c = threadIdx.x;   // 64 threads
    float acc = b2[c];
#pragma unroll
    for (int j = 0; j < 32; j++)
        acc = fmaf(fmaxf(b1[j], 0.f), W2[j * 64 + c], acc);
    g_xemp[c] = acc;
}

// ---------------------------------------------------- kernel A: MLP (tiled) --
// W2 in smem (low regs, high occupancy). Tile = 64 voxels, 256 threads.
__global__ __launch_bounds__(256)
void mlp2_kernel(const float* __restrict__ vf,
                 const float* __restrict__ W1, const float* __restrict__ b1,
                 const float* __restrict__ W2, const float* __restrict__ b2,
                 int N) {
    __shared__ __align__(16) float W1s[5][32];
    __shared__ __align__(16) float b1s[32];
    __shared__ __align__(16) float W2s[32][64];
    __shared__ __align__(16) float b2s[64];
    __shared__ __align__(16) float h_sh[32][68];
    __shared__ __align__(16) float x_sh[64][65];

    const int tid  = threadIdx.x;
    const int cp   = tid & 31;        // channels (2cp, 2cp+1)
    const int slot = tid >> 5;        // 0..7 -> voxels slot*8 .. +7
    const int v0   = blockIdx.x * 64;

    for (int i = tid; i < 160; i += 256) W1s[i / 32][i % 32] = W1[i];
    if (tid < 32) b1s[tid] = b1[tid];
    for (int i = tid; i < 2048; i += 256) W2s[i >> 6][i & 63] = W2[i];
    if (tid < 64) b2s[tid] = b2[tid];
    __syncthreads();

    // ---- phase A: hidden ----
    {
        int v = tid & 63, qr = tid >> 6;
        int gv = v0 + v;
        float f[5];
        bool ok = gv < N;
#pragma unroll
        for (int i = 0; i < 5; i++) f[i] = ok ? vf[(size_t)gv * 5 + i] : 0.f;
        u64 acc[4];
#pragma unroll
        for (int t = 0; t < 4; t++) acc[t] = *(const u64*)&b1s[qr * 8 + 2 * t];
#pragma unroll
        for (int i = 0; i < 5; i++) {
            u64 fd = dup2(f[i]);
#pragma unroll
            for (int t = 0; t < 4; t++)
                fma2(acc[t], fd, *(const u64*)&W1s[i][qr * 8 + 2 * t]);
        }
#pragma unroll
        for (int t = 0; t < 4; t++) {
            float2 h = unpk(acc[t]);
            h_sh[qr * 8 + 2 * t][v]     = fmaxf(h.x, 0.f);
            h_sh[qr * 8 + 2 * t + 1][v] = fmaxf(h.y, 0.f);
        }
    }
    __syncthreads();

    // ---- phase B: layer 2 (W2 broadcast-free from smem) ----
    {
        const int vb = slot * 8;
        float2 b2p = *(const float2*)&b2s[2 * cp];
        u64 accA[4], accB[4];
#pragma unroll
        for (int t = 0; t < 4; t++) { accA[t] = dup2(b2p.x); accB[t] = dup2(b2p.y); }
#pragma unroll 4
        for (int j = 0; j < 32; j++) {
            F4U A, B;
            A.f = *(const float4*)&h_sh[j][vb];
            B.f = *(const float4*)&h_sh[j][vb + 4];
            float2 w = *(const float2*)&W2s[j][2 * cp];
            u64 d0 = dup2(w.x), d1 = dup2(w.y);
            fma2(accA[0], A.u[0], d0); fma2(accA[1], A.u[1], d0);
            fma2(accA[2], B.u[0], d0); fma2(accA[3], B.u[1], d0);
            fma2(accB[0], A.u[0], d1); fma2(accB[1], A.u[1], d1);
            fma2(accB[2], B.u[0], d1); fma2(accB[3], B.u[1], d1);
        }
#pragma unroll
        for (int t = 0; t < 4; t++) {
            float2 a = unpk(accA[t]);
            float2 b = unpk(accB[t]);
            x_sh[vb + 2 * t][2 * cp]         = a.x;
            x_sh[vb + 2 * t + 1][2 * cp]     = a.y;
            x_sh[vb + 2 * t][2 * cp + 1]     = b.x;
            x_sh[vb + 2 * t + 1][2 * cp + 1] = b.y;
        }
    }
    __syncthreads();

    for (int idx = tid; idx < 64 * 64; idx += 256) {
        int c = idx >> 6, v = idx & 63;
        if (v0 + v < N) g_xT[(size_t)c * NPAD + v0 + v] = x_sh[v][c];
    }
}

// -------------------------------------------------- kernel B: attention -----
// QUAD per pillar: 4 threads, 16 channels each. Quad-permuted weight layouts
// for conflict-free LDS.128; quad shfl reductions; att cached in smem strip.
__global__ __launch_bounds__(128, 5)
void pillar4_kernel(const int* __restrict__ unq_cnt,
                    const float* __restrict__ Wc1, const float* __restrict__ bc1,
                    const float* __restrict__ Wc2, const float* __restrict__ bc2,
                    const float* __restrict__ Wsp, const float* __restrict__ bsp,
                    float* __restrict__ out, int U) {
    __shared__ __align__(16) ulonglong2 Wc1q[256]; // slot ((i*4+h)*4+cq)
    __shared__ __align__(16) ulonglong2 Wc2q[256]; // slot ((qq*8+hh)*4+cq)
    __shared__ __align__(16) float xemq[64];       // [i*4+cq]
    __shared__ __align__(16) u64   xemq2[32];      // [qq*4+cq] pair
    __shared__ __align__(16) u64   bcq[32];        // [qq*4+cq] 2*bc2 pair
    __shared__ float bc1s[16];
    __shared__ __align__(16) u64   Amx[32];        // conv bg coeffs
    __shared__ __align__(16) u64   wmx[7];         // (wm[t], wx[t])
    __shared__ __align__(16) u64   att_sh[8][132]; // [qq][tid]

    const int tid = threadIdx.x;
    for (int s = tid; s < 256; s += 128) {
        int cq = s & 3, h = (s >> 2) & 3, i = s >> 4;
        int c = cq * 16 + i, jb = h * 4;
        Wc1q[s] = make_ulonglong2(
            pk2(Wc1[c * 16 + jb],     Wc1[c * 16 + jb + 1]),
            pk2(Wc1[c * 16 + jb + 2], Wc1[c * 16 + jb + 3]));
    }
    for (int s = tid; s < 256; s += 128) {
        int cq = s & 3, hh = (s >> 2) & 7, qq = s >> 5;
        int q = cq * 8 + qq, j0 = 2 * hh;
        Wc2q[s] = make_ulonglong2(
            pk2(Wc2[j0 * 64 + 2 * q],       Wc2[j0 * 64 + 2 * q + 1]),
            pk2(Wc2[(j0 + 1) * 64 + 2 * q], Wc2[(j0 + 1) * 64 + 2 * q + 1]));
    }
    if (tid < 64) xemq[(tid & 15) * 4 + (tid >> 4)] = g_xemp[tid];
    if (tid < 32) {
        int q = tid, slot = (q & 7) * 4 + (q >> 3);
        xemq2[slot] = pk2(g_xemp[2 * q], g_xemp[2 * q + 1]);
        bcq[slot]   = pk2(2.f * bc2[2 * q], 2.f * bc2[2 * q + 1]);
        float am = 0.f, ax = 0.f;
#pragma unroll
        for (int t = 0; t < 7; t++) {
            int i2 = tid + t - 3;
            if (i2 >= 0 && i2 < 32) { am += Wsp[t]; ax += Wsp[7 + t]; }
        }
        Amx[tid] = pk2(am, ax);
    }
    if (tid < 16) bc1s[tid] = bc1[tid];
    if (tid < 7)  wmx[tid] = pk2(Wsp[tid], Wsp[7 + tid]);
    __syncthreads();

    const float bspv = bsp[0];
    const float NEG = __int_as_float(0xff800000);
    const int cq = tid & 3;
    const int p = blockIdx.x * 32 + (tid >> 2);
    const bool active = p < U;

    int K = 0;
    int4 e = make_int4(0, 0, 0, 0);
    if (active) {
        K = unq_cnt[p];
        K = (K < 0) ? 0 : ((K > MAXK) ? MAXK : K);
        e = g_list[p];
    }
    int vs_[4] = { e.x >> 5, e.y >> 5, e.z >> 5, e.w >> 5 };
    int bs_[4] = { e.x & 31, e.y & 31, e.z & 31, e.w & 31 };
#pragma unroll
    for (int k = 0; k < 4; k++) if (k >= K) { bs_[k] = -1000; vs_[k] = 0; }
    const float fK = (float)(NUM_BINS - K);

    const float* xthr = g_xT + (size_t)(cq * 16) * NPAD;

    // ---- phase 1: avg/max for 16 channels + catt hidden partials ---------
    u64 ap[8], aq[8];
#pragma unroll
    for (int j = 0; j < 8; j++) { ap[j] = 0ull; aq[j] = 0ull; }
    float xk0[16], xk1[16];
    {
        const float* xc = xthr;
#pragma unroll 4
        for (int i = 0; i < 16; i++) {
            float xe = xemq[i * 4 + cq];
            float s = 0.f, mx = xe;
            float a0 = 0.f, a1 = 0.f;
            if (K > 0) { a0 = xc[vs_[0]]; s += a0; mx = fmaxf(mx, a0); }
            if (K > 1) { a1 = xc[vs_[1]]; s += a1; mx = fmaxf(mx, a1); }
            if (K > 2) {
                float t2 = xc[vs_[2]]; s += t2; mx = fmaxf(mx, t2);
                if (K > 3) { float t3 = xc[vs_[3]]; s += t3; mx = fmaxf(mx, t3); }
            }
            xk0[i] = a0; xk1[i] = a1;
            float av = (s + fK * xe) * 0.03125f;
            u64 ad = dup2(av), md = dup2(mx);
            const ulonglong2* wr = &Wc1q[(i * 4) * 4 + cq];
#pragma unroll
            for (int h = 0; h < 4; h++) {
                ulonglong2 w = wr[h * 4];
                fma2(ap[2 * h],     ad, w.x);
                fma2(ap[2 * h + 1], ad, w.y);
                fma2(aq[2 * h],     md, w.x);
                fma2(aq[2 * h + 1], md, w.y);
            }
            xc += NPAD;
        }
    }

    // ---- quad butterfly reduce of hidden partials ------------------------
    float apf[16], aqf[16];
#pragma unroll
    for (int jp = 0; jp < 8; jp++) {
        float2 t = unpk(ap[jp]); apf[2 * jp] = t.x; apf[2 * jp + 1] = t.y;
        float2 u = unpk(aq[jp]); aqf[2 * jp] = u.x; aqf[2 * jp + 1] = u.y;
    }
#pragma unroll
    for (int j = 0; j < 16; j++) {
        apf[j] += __shfl_xor_sync(0xffffffffu, apf[j], 1);
        apf[j] += __shfl_xor_sync(0xffffffffu, apf[j], 2);
        aqf[j] += __shfl_xor_sync(0xffffffffu, aqf[j], 1);
        aqf[j] += __shfl_xor_sync(0xffffffffu, aqf[j], 2);
    }
    u64 gd[16];
#pragma unroll
    for (int j = 0; j < 16; j++) {
        float b = bc1s[j];
        gd[j] = dup2(fmaxf(apf[j] + b, 0.f) + fmaxf(aqf[j] + b, 0.f));
    }

    // ---- phase 2: channel attention (cache in smem) + bin statistics -----
    float ssum[4] = {0.f, 0.f, 0.f, 0.f};
    float smax4[4] = {NEG, NEG, NEG, NEG};
    float sesum = 0.f, semax = NEG;
    {
        const float* x0 = xthr;
        const float* x1 = xthr + NPAD;
#pragma unroll 2
        for (int qq = 0; qq < 8; qq++) {
            int slot = qq * 4 + cq;
            u64 acc = bcq[slot];
            const ulonglong2* w2 = &Wc2q[(qq * 8) * 4 + cq];
#pragma unroll
            for (int hh = 0; hh < 8; hh++) {
                ulonglong2 w = w2[hh * 4];
                fma2(acc, gd[2 * hh],     w.x);
                fma2(acc, gd[2 * hh + 1], w.y);
            }
            float2 A = unpk(acc);
            float a0 = sigm(A.x), a1 = sigm(A.y);
            att_sh[qq][tid] = pk2(a0, a1);
            float2 xe = unpk(xemq2[slot]);
            float y0 = a0 * xe.x, y1 = a1 * xe.y;
            sesum += y0 + y1;
            semax = fmaxf(semax, fmaxf(y0, y1));
            if (K > 0) {
                float z0 = a0 * xk0[2 * qq], z1 = a1 * xk0[2 * qq + 1];
                ssum[0] += z0 + z1;
                smax4[0] = fmaxf(smax4[0], fmaxf(z0, z1));
            }
            if (K > 1) {
                float z0 = a0 * xk1[2 * qq], z1 = a1 * xk1[2 * qq + 1];
                ssum[1] += z0 + z1;
                smax4[1] = fmaxf(smax4[1], fmaxf(z0, z1));
            }
            if (K > 2) {
                float z0 = a0 * x0[vs_[2]], z1 = a1 * x1[vs_[2]];
                ssum[2] += z0 + z1;
                smax4[2] = fmaxf(smax4[2], fmaxf(z0, z1));
                if (K > 3) {
                    float w0 = a0 * x0[vs_[3]], w1 = a1 * x1[vs_[3]];
                    ssum[3] += w0 + w1;
                    smax4[3] = fmaxf(smax4[3], fmaxf(w0, w1));
                }
            }
            x0 += 2 * NPAD;
            x1 += 2 * NPAD;
        }
    }

    // ---- quad reduce bin stats ------------------------------------------
#pragma unroll
    for (int r = 1; r <= 2; r <<= 1) {
#pragma unroll
        for (int k = 0; k < 4; k++) {
            ssum[k] += __shfl_xor_sync(0xffffffffu, ssum[k], r);
            smax4[k] = fmaxf(smax4[k], __shfl_xor_sync(0xffffffffu, smax4[k], r));
        }
        sesum += __shfl_xor_sync(0xffffffffu, sesum, r);
        semax = fmaxf(semax, __shfl_xor_sync(0xffffffffu, semax, r));
    }

    // ---- bin attention: bg + sparse corrections (redundant per thread) ---
    const float se_m = sesum * (1.f / 64.f);
    const float se_x = semax;
    const u64 semx = pk2(se_m, se_x);
    u64 dk2[4];
#pragma unroll
    for (int k = 0; k < 4; k++)
        dk2[k] = pk2(ssum[k] * (1.f / 64.f) - se_m, smax4[k] - se_x);

    float argk[4] = {0.f, 0.f, 0.f, 0.f};
    float emax = NEG, emin = -NEG;
#pragma unroll 8
    for (int b = 0; b < 32; b++) {
        u64 a2 = pk2(bspv, 0.f);
        fma2(a2, semx, Amx[b]);
        bool occ = false;
        bool hit[4];
#pragma unroll
        for (int k = 0; k < 4; k++) {
            int d = bs_[k] - b;
            if ((unsigned)(d + 3) <= 6u) fma2(a2, dk2[k], wmx[d + 3]);
            hit[k] = (d == 0);
            occ |= hit[k];
        }
        float2 av = unpk(a2);
        float a = av.x + av.y;
#pragma unroll
        for (int k = 0; k < 4; k++) argk[k] = hit[k] ? a : argk[k];
        emax = occ ? emax : fmaxf(emax, a);
        emin = occ ? emin : fminf(emin, a);
    }
    float sigk[4];
#pragma unroll
    for (int k = 0; k < 4; k++) sigk[k] = sigm(argk[k]);
    const float sigeP = sigm(emax);    // y_empty >= 0
    const float sigeN = sigm(emin);    // y_empty <  0

    // ---- phase 3: final max over bins, att from smem, direct store -------
    if (active) {
        const float* x0 = xthr;
        const float* x1 = xthr + NPAD;
        float o[16];
#pragma unroll 2
        for (int qq = 0; qq < 8; qq++) {
            float2 A = unpk(att_sh[qq][tid]);
            float2 xe = unpk(xemq2[qq * 4 + cq]);
            float M0 = xe.x * ((xe.x >= 0.f) ? sigeP : sigeN);
            float M1 = xe.y * ((xe.y >= 0.f) ? sigeP : sigeN);
            if (K > 0) {
                M0 = fmaxf(M0, xk0[2 * qq] * sigk[0]);
                M1 = fmaxf(M1, xk0[2 * qq + 1] * sigk[0]);
            }
            if (K > 1) {
                M0 = fmaxf(M0, xk1[2 * qq] * sigk[1]);
                M1 = fmaxf(M1, xk1[2 * qq + 1] * sigk[1]);
            }
            if (K > 2) {
                M0 = fmaxf(M0, x0[vs_[2]] * sigk[2]);
                M1 = fmaxf(M1, x1[vs_[2]] * sigk[2]);
                if (K > 3) {
                    M0 = fmaxf(M0, x0[vs_[3]] * sigk[3]);
                    M1 = fmaxf(M1, x1[vs_[3]] * sigk[3]);
                }
            }
            o[2 * qq]     = A.x * M0;
            o[2 * qq + 1] = A.y * M1;
            x0 += 2 * NPAD;
            x1 += 2 * NPAD;
        }
        float4* dst = (float4*)(out + (size_t)p * 64 + cq * 16);
#pragma unroll
        for (int t = 0; t < 4; t++)
            dst[t] = make_float4(o[4 * t], o[4 * t + 1], o[4 * t + 2], o[4 * t + 3]);
    }
}

// ------------------------------------------------------------------ launch --
extern "C" void kernel_launch(void* const* d_in, const int* in_sizes, int n_in,
                              void* d_out, int out_size) {
    const float* vf      = (const float*)d_in[0];
    const int*   coords  = (const int*)  d_in[1];
    const int*   unq_inv = (const int*)  d_in[3];
    const int*   unq_cnt = (const int*)  d_in[4];
    const float* W1  = (const float*)d_in[5];
    const float* b1  = (const float*)d_in[6];
    const float* W2  = (const float*)d_in[7];
    const float* b2  = (const float*)d_in[8];
    const float* Wc1 = (const float*)d_in[9];
    const float* bc1 = (const float*)d_in[10];
    const float* Wc2 = (const float*)d_in[11];
    const float* bc2 = (const float*)d_in[12];
    const float* Wsp = (const float*)d_in[13];
    const float* bsp = (const float*)d_in[14];
    float* out = (float*)d_out;

    int N = in_sizes[0] / 5;
    if (N > NMAXV) N = NMAXV;
    int U = in_sizes[2];
    if (U > MAXU) U = MAXU;

    void* cnt_ptr = nullptr;
    cudaGetSymbolAddress(&cnt_ptr, g_cnt);
    cudaMemsetAsync(cnt_ptr, 0, (size_t)U * sizeof(int));

    scatter_kernel<<<(N + 255) / 256, 256>>>(unq_inv, coords, N);
    xemp_kernel<<<1, 64>>>(b1, W2, b2);
    mlp2_kernel<<<(N + 63) / 64, 256>>>(vf, W1, b1, W2, b2, N);
    pillar4_kernel<<<(U + 31) / 32, 128>>>(unq_cnt, Wc1, bc1, Wc2, bc2,
                                           Wsp, bsp, out, U);

    long long feat = (long long)U * 64;
    if ((long long)out_size > feat) {
        long long extra = (long long)out_size - feat;
        int n = (extra > U) ? U : (int)extra;
        mask_kernel<<<(n + 255) / 256, 256>>>(unq_cnt, out, feat, n);
    }
}